// round 1
// baseline (speedup 1.0000x reference)
#include <cuda_runtime.h>
#include <math.h>

// Fused block-DCT + soft-histogram kernel.
//
// Stage 1: 8x8 block DCT of [16,256,256] input with the provided [8,8,1,64]
//          basis  -> x[b, block, k]  (32x32 blocks per image, 64 channels)
// Stage 2: soft histogram: gamma=1e6 makes sigmoid(g*(x-bin)) exactly 0/1 in
//          fp32 unless |x-bin| < ~3e-5. So each element contributes +1/1024 to
//          bin floor(x)+60, with rare exact-sigmoid corrections at bin edges.
//
// Output layout: [16, 120, 64, 1] float32.

#define NBATCH   16
#define NSLICE   16      // slices per image; each slice = 2 block-rows (64 blocks)
#define NTHREADS 256
#define NK       64
#define NBINS    120
#define INV1024  (1.0f / 1024.0f)

__global__ void __launch_bounds__(NTHREADS, 2)
dct_hist_kernel(const float* __restrict__ in,
                const float* __restrict__ basis,
                float* __restrict__ out)
{
    extern __shared__ float smem[];
    float* B_s  = smem;                 // [64 p][64 k]          4096 floats
    float* in_s = smem + 4096;          // [64 p][64 blk] pad65  4160 floats
    float* hist = smem + 4096 + 4160;   // [64 k][120 t]         7680 floats

    const int b     = blockIdx.x;   // batch
    const int slice = blockIdx.y;   // 2 block-rows
    const int tid   = threadIdx.x;

    // Zero histogram
    for (int i = tid; i < NK * NBINS; i += NTHREADS) hist[i] = 0.0f;

    // Load basis [p][k] (already laid out as dx,dy,1,k -> p,k)
    for (int i = tid; i < 4096; i += NTHREADS) B_s[i] = basis[i];

    // Load input tile: 16 pixel rows x 256 cols, transposed to [p][block]
    const float* src = in + ((size_t)b * 256 + (size_t)slice * 16) * 256;
    for (int i = tid; i < 16 * 256; i += NTHREADS) {
        int row = i >> 8;          // 0..15
        int col = i & 255;         // 0..255
        float v = src[i];
        int p   = ((row & 7) << 3) | (col & 7);        // 0..63
        int blk = ((row >> 3) << 5) | (col >> 3);      // 0..63
        in_s[p * 65 + blk] = v;
    }
    __syncthreads();

    // DCT: thread -> (block = tid&63, 16 consecutive k)
    const int blk = tid & 63;
    const int k0  = (tid >> 6) << 4;   // 0,16,32,48 (constant per warp)

    float acc[16];
#pragma unroll
    for (int j = 0; j < 16; j++) acc[j] = 0.0f;

#pragma unroll 4
    for (int p = 0; p < 64; p++) {
        float a = in_s[p * 65 + blk];
        const float4* bp = reinterpret_cast<const float4*>(B_s + (p << 6) + k0);
        float4 b0 = bp[0], b1 = bp[1], b2 = bp[2], b3 = bp[3];
        acc[0]  += a * b0.x;  acc[1]  += a * b0.y;
        acc[2]  += a * b0.z;  acc[3]  += a * b0.w;
        acc[4]  += a * b1.x;  acc[5]  += a * b1.y;
        acc[6]  += a * b1.z;  acc[7]  += a * b1.w;
        acc[8]  += a * b2.x;  acc[9]  += a * b2.y;
        acc[10] += a * b2.z;  acc[11] += a * b2.w;
        acc[12] += a * b3.x;  acc[13] += a * b3.y;
        acc[14] += a * b3.z;  acc[15] += a * b3.w;
    }

    // Histogram scatter
#pragma unroll
    for (int j = 0; j < 16; j++) {
        float v  = acc[j];
        float fl = floorf(v);
        int   ti = (int)fl + 60;          // bin index where v lives
        float d  = v - fl;                // in [0,1)
        const int kk = k0 + j;

        if (d > 3e-5f && d < 1.0f - 3e-5f) {
            // Both boundary sigmoids saturate exactly (to 1.0f / ~0): hard count.
            if ((unsigned)ti < (unsigned)NBINS)
                atomicAdd(&hist[kk * NBINS + ti], INV1024);
        } else {
            // Soft edge: compute the two boundary sigmoids exactly (fp32,
            // elementwise identical math to the reference).
            float z0 = 1e6f * (v - (float)(ti - 60));   // >= 0 side
            float z1 = 1e6f * (v - (float)(ti - 59));   // <= 0 side
            float s0 = (z0 >= 30.0f) ? 1.0f : (1.0f / (1.0f + expf(-z0)));
            float s1;
            if (z1 <= -30.0f) s1 = 0.0f;
            else { float e = expf(z1); s1 = e / (1.0f + e); }

            float w_lo  = (1.0f - s0) * INV1024;  // bin ti-1
            float w_mid = (s0 - s1)   * INV1024;  // bin ti
            float w_hi  = s1          * INV1024;  // bin ti+1
            if ((unsigned)(ti - 1) < (unsigned)NBINS && w_lo != 0.0f)
                atomicAdd(&hist[kk * NBINS + (ti - 1)], w_lo);
            if ((unsigned)ti < (unsigned)NBINS && w_mid != 0.0f)
                atomicAdd(&hist[kk * NBINS + ti], w_mid);
            if ((unsigned)(ti + 1) < (unsigned)NBINS && w_hi != 0.0f)
                atomicAdd(&hist[kk * NBINS + (ti + 1)], w_hi);
        }
    }
    __syncthreads();

    // Accumulate CTA-local histogram into global output [b, t, k]
    float* outb = out + (size_t)b * NBINS * NK;
    for (int i = tid; i < NK * NBINS; i += NTHREADS) {
        float h = hist[i];
        if (h != 0.0f) {
            int k = i / NBINS;
            int t = i - k * NBINS;
            atomicAdd(&outb[t * NK + k], h);
        }
    }
}

extern "C" void kernel_launch(void* const* d_in, const int* in_sizes, int n_in,
                              void* d_out, int out_size)
{
    const float* in    = (const float*)d_in[0];   // [16,256,256,1]
    const float* basis = (const float*)d_in[1];   // [8,8,1,64]
    float* out = (float*)d_out;                   // [16,120,64,1]

    (void)in_sizes; (void)n_in;

    const int smem_bytes = (4096 + 4160 + 7680) * (int)sizeof(float);  // 63744
    cudaFuncSetAttribute(dct_hist_kernel,
                         cudaFuncAttributeMaxDynamicSharedMemorySize,
                         smem_bytes);

    cudaMemsetAsync(d_out, 0, (size_t)out_size * sizeof(float), 0);

    dim3 grid(NBATCH, NSLICE);
    dct_hist_kernel<<<grid, NTHREADS, smem_bytes>>>(in, basis, out);
}

// round 2
// speedup vs baseline: 1.4878x; 1.4878x over previous
#include <cuda_runtime.h>
#include <math.h>

// Fused block-DCT + soft-histogram, v2: occupancy-oriented decomposition.
//
// Grid (16 batch, 32 block-rows, 2 k-halves) = 1024 CTAs x 256 threads.
// Each CTA: one 8-pixel-row strip (32 blocks) x 32 DCT channels.
// Thread = (block = tid&31, 4 consecutive k). The 64-term DCT dot product is
// accumulated in ascending-p order (bit-identical to the v1 kernel that
// matched the reference to 6.4e-9).
//
// gamma=1e6 saturates the sigmoids to exact 0/1 in fp32 except within ~3e-5
// of an integer threshold, so the soft histogram is a hard count (+1/1024,
// exact dyadic => order-independent atomics) plus rare exact-sigmoid edges.

#define NBINS   120
#define INV1024 (1.0f / 1024.0f)

__global__ void __launch_bounds__(256, 7)
dct_hist_kernel(const float* __restrict__ in,
                const float* __restrict__ basis,
                float* __restrict__ out)
{
    __shared__ float B_s[64 * 32];      // basis [p][kk] for this k-half
    __shared__ float in_s[64 * 33];     // input [p][blk], pad 33 (conflict-free)
    __shared__ float hist[32 * NBINS];  // [kk][t]

    const int b   = blockIdx.x;   // batch
    const int row = blockIdx.y;   // block-row 0..31
    const int kh  = blockIdx.z;   // k-half 0/1
    const int tid = threadIdx.x;

    // Zero histogram
    #pragma unroll
    for (int i = tid; i < 32 * NBINS; i += 256) hist[i] = 0.0f;

    // Load basis half: B_s[p*32+kk] = basis[p*64 + kh*32 + kk]   (coalesced)
    #pragma unroll
    for (int i = tid; i < 64 * 32; i += 256) {
        int p  = i >> 5;
        int kk = i & 31;
        B_s[i] = basis[(p << 6) + (kh << 5) + kk];
    }

    // Load input strip: 8 pixel rows x 256 cols, transpose to [p][blk]
    const float4* src = reinterpret_cast<const float4*>(
        in + ((size_t)b * 256 + (size_t)row * 8) * 256);
    #pragma unroll
    for (int i = tid; i < 512; i += 256) {
        float4 v  = src[i];
        int r     = i >> 6;              // pixel row 0..7  (= dx)
        int c0    = (i & 63) << 2;       // col 0..252, step 4 (within one block)
        int blk   = c0 >> 3;             // 0..31
        int pbase = (r << 3) | (c0 & 7); // p = dx*8 + dy
        in_s[(pbase + 0) * 33 + blk] = v.x;
        in_s[(pbase + 1) * 33 + blk] = v.y;
        in_s[(pbase + 2) * 33 + blk] = v.z;
        in_s[(pbase + 3) * 33 + blk] = v.w;
    }
    __syncthreads();

    // DCT: thread -> (blk = lane, k0 = warp*4); 4 accumulators
    const int blk = tid & 31;
    const int k0  = (tid >> 5) << 2;   // 0,4,...,28 (constant per warp)

    float a0 = 0.0f, a1 = 0.0f, a2 = 0.0f, a3 = 0.0f;
    #pragma unroll 8
    for (int p = 0; p < 64; p++) {
        float a  = in_s[p * 33 + blk];                       // conflict-free
        float4 q = *reinterpret_cast<const float4*>(B_s + (p << 5) + k0); // bcast
        a0 += a * q.x;  a1 += a * q.y;  a2 += a * q.z;  a3 += a * q.w;
    }

    // Histogram scatter (4 values)
    float vals[4] = {a0, a1, a2, a3};
    #pragma unroll
    for (int j = 0; j < 4; j++) {
        float v  = vals[j];
        float fl = floorf(v);
        int   ti = (int)fl + 60;
        float d  = v - fl;
        const int kk = k0 + j;

        if (d > 3e-5f && d < 1.0f - 3e-5f) {
            if ((unsigned)ti < (unsigned)NBINS)
                atomicAdd(&hist[kk * NBINS + ti], INV1024);
        } else {
            // Exact fp32 sigmoids at the two neighboring thresholds
            float z0 = 1e6f * (v - (float)(ti - 60));
            float z1 = 1e6f * (v - (float)(ti - 59));
            float s0 = (z0 >= 30.0f) ? 1.0f : (1.0f / (1.0f + expf(-z0)));
            float s1;
            if (z1 <= -30.0f) s1 = 0.0f;
            else { float e = expf(z1); s1 = e / (1.0f + e); }

            float w_lo  = (1.0f - s0) * INV1024;
            float w_mid = (s0 - s1)   * INV1024;
            float w_hi  = s1          * INV1024;
            if ((unsigned)(ti - 1) < (unsigned)NBINS && w_lo != 0.0f)
                atomicAdd(&hist[kk * NBINS + (ti - 1)], w_lo);
            if ((unsigned)ti < (unsigned)NBINS && w_mid != 0.0f)
                atomicAdd(&hist[kk * NBINS + ti], w_mid);
            if ((unsigned)(ti + 1) < (unsigned)NBINS && w_hi != 0.0f)
                atomicAdd(&hist[kk * NBINS + (ti + 1)], w_hi);
        }
    }
    __syncthreads();

    // Flush CTA histogram to global [b, t, k]
    float* outb = out + (size_t)b * NBINS * 64;
    #pragma unroll
    for (int i = tid; i < 32 * NBINS; i += 256) {
        float h = hist[i];
        if (h != 0.0f) {
            int kk = i / NBINS;
            int t  = i - kk * NBINS;
            atomicAdd(&outb[t * 64 + (kh << 5) + kk], h);
        }
    }
}

extern "C" void kernel_launch(void* const* d_in, const int* in_sizes, int n_in,
                              void* d_out, int out_size)
{
    const float* in    = (const float*)d_in[0];   // [16,256,256,1]
    const float* basis = (const float*)d_in[1];   // [8,8,1,64]
    float* out = (float*)d_out;                   // [16,120,64,1]
    (void)in_sizes; (void)n_in;

    cudaMemsetAsync(d_out, 0, (size_t)out_size * sizeof(float), 0);

    dim3 grid(16, 32, 2);
    dct_hist_kernel<<<grid, 256>>>(in, basis, out);
}

// round 3
// speedup vs baseline: 2.0722x; 1.3928x over previous
#include <cuda_runtime.h>
#include <math.h>

// Fused block-DCT + soft-histogram, v3: no shared-memory histogram.
//
// Grid (16 batch, 32 block-rows) = 512 CTAs x 256 threads.
// Thread = (block = lane, 8 consecutive k per warp). Per-output DCT sum is
// the same ascending-p FMA chain as v1/v2 (bit-identical, rel_err ~7e-9).
//
// Histogram: gamma=1e6 saturates sigmoids to exact 0/1 except within ~3e-5
// of an integer threshold -> each element is a hard count (+1/1024, exact
// dyadic). Since a warp's 32 lanes share the same k, __match_any_sync groups
// lanes hitting the same bin and one leader issues a single global
// atomicAdd (fire-and-forget REDG). Rare soft-edge elements compute the two
// boundary sigmoids exactly and add their fractional weights directly.

#define NBINS   120
#define INV1024 (1.0f / 1024.0f)

__global__ void __launch_bounds__(256, 4)
dct_hist_kernel(const float* __restrict__ in,
                const float* __restrict__ basis,
                float* __restrict__ out)
{
    __shared__ float B_s[64 * 64];     // basis [p][k]   16 KB
    __shared__ float in_s[64 * 33];    // input [p][blk] pad 33, 8.4 KB

    const int b   = blockIdx.x;   // batch
    const int row = blockIdx.y;   // block-row 0..31
    const int tid = threadIdx.x;

    // Load basis [p][k] (coalesced, layout matches dx,dy,1,k -> p,k)
    #pragma unroll
    for (int i = tid; i < 4096; i += 256) B_s[i] = basis[i];

    // Load input strip: 8 pixel rows x 256 cols, transpose to [p][blk]
    const float4* src = reinterpret_cast<const float4*>(
        in + ((size_t)b * 256 + (size_t)row * 8) * 256);
    #pragma unroll
    for (int i = tid; i < 512; i += 256) {
        float4 v  = src[i];
        int r     = i >> 6;              // pixel row 0..7  (= dx)
        int c0    = (i & 63) << 2;       // col within row, step 4
        int blk   = c0 >> 3;             // 0..31
        int pbase = (r << 3) | (c0 & 7); // p = dx*8 + dy
        in_s[(pbase + 0) * 33 + blk] = v.x;
        in_s[(pbase + 1) * 33 + blk] = v.y;
        in_s[(pbase + 2) * 33 + blk] = v.z;
        in_s[(pbase + 3) * 33 + blk] = v.w;
    }
    __syncthreads();

    // DCT: thread -> (blk = lane, 8 consecutive k starting at warp*8)
    const int lane = tid & 31;
    const int k0   = (tid >> 5) << 3;   // 0,8,...,56 (uniform per warp)

    float a0 = 0.f, a1 = 0.f, a2 = 0.f, a3 = 0.f;
    float a4 = 0.f, a5 = 0.f, a6 = 0.f, a7 = 0.f;
    #pragma unroll 8
    for (int p = 0; p < 64; p++) {
        float a = in_s[p * 33 + lane];                    // conflict-free
        const float4* bp = reinterpret_cast<const float4*>(B_s + (p << 6) + k0);
        float4 q0 = bp[0], q1 = bp[1];                    // warp-uniform (bcast)
        a0 += a * q0.x;  a1 += a * q0.y;  a2 += a * q0.z;  a3 += a * q0.w;
        a4 += a * q1.x;  a5 += a * q1.y;  a6 += a * q1.z;  a7 += a * q1.w;
    }

    // Scatter: warp-aggregated global atomics
    float* outb = out + (size_t)b * NBINS * 64;
    float vals[8] = {a0, a1, a2, a3, a4, a5, a6, a7};

    #pragma unroll
    for (int j = 0; j < 8; j++) {
        float v  = vals[j];
        float fl = floorf(v);
        int   ti = (int)fl + 60;
        float d  = v - fl;
        const int kk = k0 + j;            // uniform per warp

        bool hard = (d > 3e-5f) && (d < 1.0f - 3e-5f);
        unsigned hard_mask = __ballot_sync(0xffffffffu, hard);

        if (hard) {
            unsigned grp = __match_any_sync(hard_mask, ti);
            int leader   = __ffs(grp) - 1;
            if (lane == leader && (unsigned)ti < (unsigned)NBINS) {
                float w = (float)__popc(grp) * INV1024;
                atomicAdd(&outb[ti * 64 + kk], w);
            }
        } else {
            // Soft edge: exact fp32 sigmoids at the two nearest thresholds.
            float z0 = 1e6f * (v - (float)(ti - 60));
            float z1 = 1e6f * (v - (float)(ti - 59));
            float s0 = (z0 >= 30.0f) ? 1.0f : (1.0f / (1.0f + expf(-z0)));
            float s1;
            if (z1 <= -30.0f) s1 = 0.0f;
            else { float e = expf(z1); s1 = e / (1.0f + e); }

            float w_lo  = (1.0f - s0) * INV1024;  // bin ti-1
            float w_mid = (s0 - s1)   * INV1024;  // bin ti
            float w_hi  = s1          * INV1024;  // bin ti+1
            if ((unsigned)(ti - 1) < (unsigned)NBINS && w_lo != 0.0f)
                atomicAdd(&outb[(ti - 1) * 64 + kk], w_lo);
            if ((unsigned)ti < (unsigned)NBINS && w_mid != 0.0f)
                atomicAdd(&outb[ti * 64 + kk], w_mid);
            if ((unsigned)(ti + 1) < (unsigned)NBINS && w_hi != 0.0f)
                atomicAdd(&outb[(ti + 1) * 64 + kk], w_hi);
        }
    }
}

extern "C" void kernel_launch(void* const* d_in, const int* in_sizes, int n_in,
                              void* d_out, int out_size)
{
    const float* in    = (const float*)d_in[0];   // [16,256,256,1]
    const float* basis = (const float*)d_in[1];   // [8,8,1,64]
    float* out = (float*)d_out;                   // [16,120,64,1]
    (void)in_sizes; (void)n_in;

    cudaMemsetAsync(d_out, 0, (size_t)out_size * sizeof(float), 0);

    dim3 grid(16, 32);
    dct_hist_kernel<<<grid, 256>>>(in, basis, out);
}